// round 5
// baseline (speedup 1.0000x reference)
#include <cuda_runtime.h>
#include <cuda_bf16.h>
#include <cstdint>

#define D4 32               // float4 per full row (D=128)
#define QPC 8               // float4-quads per CTA (32 columns = 128B/row)
#define THREADS 1024
#define RB (THREADS / QPC)  // 128 distinct row-bases
#define ROWS_PER_CTA 512
#define RITER (ROWS_PER_CTA / RB)   // 4
#define NWARP (THREADS / 32)

__device__ __forceinline__ void cp_async16(uint32_t smem_addr, const void* gmem) {
    asm volatile("cp.async.cg.shared.global [%0], [%1], 16;\n"
                 :: "r"(smem_addr), "l"(gmem) : "memory");
}

__device__ __forceinline__ uint32_t mapa_u32(uint32_t local, uint32_t rank) {
    uint32_t r;
    asm volatile("mapa.shared::cluster.u32 %0, %1, %2;" : "=r"(r) : "r"(local), "r"(rank));
    return r;
}

__device__ __forceinline__ void st_cluster_b64(uint32_t addr, uint64_t v) {
    asm volatile("st.shared::cluster.b64 [%0], %1;" :: "r"(addr), "l"(v) : "memory");
}

__device__ __forceinline__ uint64_t pack2(float a, float b) {
    uint64_t r;
    asm("mov.b64 %0, {%1, %2};" : "=l"(r) : "f"(a), "f"(b));
    return r;
}

__global__ __launch_bounds__(THREADS, 2) __cluster_dims__(2, 1, 1)
void graphnorm_mbar(const float* __restrict__ x,
                    const float* __restrict__ gamma,
                    const float* __restrict__ beta,
                    const int* __restrict__ batch,
                    float* __restrict__ out)
{
    extern __shared__ float4 tile[];                 // [ROWS_PER_CTA][QPC] = 64 KB
    __shared__ float4 psum[NWARP][QPC];
    __shared__ float4 psq [NWARP][QPC];
    __shared__ float4 recv_sum[QPC];                 // peer pushes its partial here
    __shared__ float4 recv_sq [QPC];
    __shared__ float4 smean[QPC], sinv[QPC];
    __shared__ __align__(8) uint64_t mbar;

    const int rk   = blockIdx.x;                     // cluster rank: row half 0/1
    const int g    = blockIdx.y;
    const int cb   = blockIdx.z;                     // column block 0..3
    const int quad = threadIdx.x & (QPC - 1);        // 0..7
    const int rb   = threadIdx.x >> 3;               // 0..127
    const int warp = threadIdx.x >> 5;
    const int lane = threadIdx.x & 31;

    const uint32_t mbar_addr = (uint32_t)__cvta_generic_to_shared(&mbar);

    // init mbarrier before any cluster traffic (count = 8 arrivals from peer)
    if (threadIdx.x == 0) {
        asm volatile("mbarrier.init.shared.b64 [%0], %1;" :: "r"(mbar_addr), "r"(8) : "memory");
    }

    const int start = batch[g];
    const int end   = batch[g + 1];
    const int cnt   = end - start;
    const float fcnt = (float)cnt;
    const int h       = cnt >> 1;
    const int myStart = start + rk * h;
    const int myCnt   = rk ? (cnt - h) : h;

    const float4* __restrict__ xv = (const float4*)x;
    float4* __restrict__ ov = (float4*)out;
    const long colq = (long)cb * QPC + quad;         // float4 col 0..31

    // ---- async loads: two commit groups (first half / second half) ----
    uint32_t tbase = (uint32_t)__cvta_generic_to_shared(tile);
    #pragma unroll
    for (int i = 0; i < RITER / 2; i++) {
        int r = rb + i * RB;
        if (r < myCnt)
            cp_async16(tbase + (uint32_t)(r * QPC + quad) * 16u,
                       &xv[(long)(myStart + r) * D4 + colq]);
    }
    asm volatile("cp.async.commit_group;\n" ::: "memory");
    #pragma unroll
    for (int i = RITER / 2; i < RITER; i++) {
        int r = rb + i * RB;
        if (r < myCnt)
            cp_async16(tbase + (uint32_t)(r * QPC + quad) * 16u,
                       &xv[(long)(myStart + r) * D4 + colq]);
    }
    asm volatile("cp.async.commit_group;\n" ::: "memory");

    // cluster.sync hidden under the in-flight cp.async traffic:
    // guarantees peer's mbarrier is initialized before we arrive on it.
    asm volatile("barrier.cluster.arrive.aligned;" ::: "memory");
    asm volatile("barrier.cluster.wait.aligned;" ::: "memory");

    float4 s = make_float4(0.f, 0.f, 0.f, 0.f);
    float4 q = make_float4(0.f, 0.f, 0.f, 0.f);

    // ---- first half arrives -> accumulate while second half streams ----
    asm volatile("cp.async.wait_group 1;\n" ::: "memory");
    __syncthreads();
    #pragma unroll
    for (int i = 0; i < RITER / 2; i++) {
        int r = rb + i * RB;
        if (r < myCnt) {
            float4 v = tile[r * QPC + quad];
            s.x += v.x; s.y += v.y; s.z += v.z; s.w += v.w;
            q.x += v.x * v.x; q.y += v.y * v.y; q.z += v.z * v.z; q.w += v.w * v.w;
        }
    }
    asm volatile("cp.async.wait_group 0;\n" ::: "memory");
    __syncthreads();
    #pragma unroll
    for (int i = RITER / 2; i < RITER; i++) {
        int r = rb + i * RB;
        if (r < myCnt) {
            float4 v = tile[r * QPC + quad];
            s.x += v.x; s.y += v.y; s.z += v.z; s.w += v.w;
            q.x += v.x * v.x; q.y += v.y * v.y; q.z += v.z * v.z; q.w += v.w * v.w;
        }
    }

    // ---- warp reduce: lanes {quad, quad+8, quad+16, quad+24} share a column ----
    #pragma unroll
    for (int off = 8; off <= 16; off <<= 1) {
        s.x += __shfl_xor_sync(0xffffffffu, s.x, off);
        s.y += __shfl_xor_sync(0xffffffffu, s.y, off);
        s.z += __shfl_xor_sync(0xffffffffu, s.z, off);
        s.w += __shfl_xor_sync(0xffffffffu, s.w, off);
        q.x += __shfl_xor_sync(0xffffffffu, q.x, off);
        q.y += __shfl_xor_sync(0xffffffffu, q.y, off);
        q.z += __shfl_xor_sync(0xffffffffu, q.z, off);
        q.w += __shfl_xor_sync(0xffffffffu, q.w, off);
    }
    if (lane < QPC) { psum[warp][quad] = s; psq[warp][quad] = q; }
    __syncthreads();

    // ---- CTA reduce (threads 0..7), push partials into PEER's smem ----
    if (threadIdx.x < QPC) {
        float4 ts = make_float4(0.f, 0.f, 0.f, 0.f);
        float4 tq = make_float4(0.f, 0.f, 0.f, 0.f);
        #pragma unroll
        for (int w = 0; w < NWARP; w++) {
            float4 a = psum[w][threadIdx.x];
            float4 b = psq [w][threadIdx.x];
            ts.x += a.x; ts.y += a.y; ts.z += a.z; ts.w += a.w;
            tq.x += b.x; tq.y += b.y; tq.z += b.z; tq.w += b.w;
        }

        const uint32_t peer = (uint32_t)(rk ^ 1);
        uint32_t ps_addr = mapa_u32((uint32_t)__cvta_generic_to_shared(&recv_sum[threadIdx.x]), peer);
        uint32_t pq_addr = mapa_u32((uint32_t)__cvta_generic_to_shared(&recv_sq [threadIdx.x]), peer);
        st_cluster_b64(ps_addr,      pack2(ts.x, ts.y));
        st_cluster_b64(ps_addr + 8,  pack2(ts.z, ts.w));
        st_cluster_b64(pq_addr,      pack2(tq.x, tq.y));
        st_cluster_b64(pq_addr + 8,  pack2(tq.z, tq.w));

        uint32_t peer_mbar = mapa_u32(mbar_addr, peer);
        asm volatile("mbarrier.arrive.release.cluster.shared::cluster.b64 _, [%0];"
                     :: "r"(peer_mbar) : "memory");

        // ---- wait for peer's push (fast-path ~90 cyc) ----
        asm volatile(
            "{\n\t.reg .pred p;\n\t"
            "WAITL_%=:\n\t"
            "mbarrier.try_wait.parity.acquire.cluster.shared::cta.b64 p, [%0], 0;\n\t"
            "@!p bra WAITL_%=;\n\t}"
            :: "r"(mbar_addr) : "memory");

        float4 a = recv_sum[threadIdx.x];
        float4 b = recv_sq [threadIdx.x];
        ts.x += a.x; ts.y += a.y; ts.z += a.z; ts.w += a.w;
        tq.x += b.x; tq.y += b.y; tq.z += b.z; tq.w += b.w;

        float4 m, iv;
        m.x = ts.x / fcnt; m.y = ts.y / fcnt; m.z = ts.z / fcnt; m.w = ts.w / fcnt;
        float denom = fcnt - 1.0f;
        iv.x = 1.0f / (sqrtf(fmaxf((tq.x - fcnt * m.x * m.x) / denom, 0.f)) + 1e-5f);
        iv.y = 1.0f / (sqrtf(fmaxf((tq.y - fcnt * m.y * m.y) / denom, 0.f)) + 1e-5f);
        iv.z = 1.0f / (sqrtf(fmaxf((tq.z - fcnt * m.z * m.z) / denom, 0.f)) + 1e-5f);
        iv.w = 1.0f / (sqrtf(fmaxf((tq.w - fcnt * m.w * m.w) / denom, 0.f)) + 1e-5f);
        smean[threadIdx.x] = m;
        sinv [threadIdx.x] = iv;
    }
    __syncthreads();

    // ---- normalize from smem tile, write out; no trailing cluster sync ----
    const float4 g4 = ((const float4*)gamma)[colq];
    const float4 b4 = ((const float4*)beta)[colq];
    const float4 m  = smean[quad];
    const float4 iv = sinv [quad];

    #pragma unroll
    for (int i = 0; i < RITER; i++) {
        int r = rb + i * RB;
        if (r < myCnt) {
            float4 v = tile[r * QPC + quad];
            float4 o;
            o.x = g4.x * (v.x - m.x) * iv.x + b4.x;
            o.y = g4.y * (v.y - m.y) * iv.y + b4.y;
            o.z = g4.z * (v.z - m.z) * iv.z + b4.z;
            o.w = g4.w * (v.w - m.w) * iv.w + b4.w;
            ov[(long)(myStart + r) * D4 + colq] = o;
        }
    }
}

extern "C" void kernel_launch(void* const* d_in, const int* in_sizes, int n_in,
                              void* d_out, int out_size)
{
    const float* x     = (const float*)d_in[0];
    const float* gamma = (const float*)d_in[1];
    const float* beta  = (const float*)d_in[2];
    const int*   batch = (const int*)d_in[3];
    float* out = (float*)d_out;

    const int G = in_sizes[3] - 1;
    const size_t smem = (size_t)ROWS_PER_CTA * QPC * sizeof(float4);   // 64 KB

    cudaFuncSetAttribute(graphnorm_mbar,
                         cudaFuncAttributeMaxDynamicSharedMemorySize, (int)smem);

    dim3 grid(2, G, D4 / QPC);   // (row-half, graph, column-block)
    graphnorm_mbar<<<grid, THREADS, smem>>>(x, gamma, beta, batch, out);
}

// round 6
// speedup vs baseline: 1.2280x; 1.2280x over previous
#include <cuda_runtime.h>
#include <cuda_bf16.h>

#define D4 32               // float4 per full row (D=128)
#define QPC 8               // float4-quads per CTA (32 cols = 128B contiguous/row)
#define THREADS 512
#define RB (THREADS / QPC)  // 64 row-bases
#define NWARP (THREADS / 32)

__global__ __launch_bounds__(THREADS, 4)
void graphnorm_l2(const float* __restrict__ x,
                  const float* __restrict__ gamma,
                  const float* __restrict__ beta,
                  const int* __restrict__ batch,
                  float* __restrict__ out)
{
    __shared__ float4 psum[NWARP][QPC];
    __shared__ float4 psq [NWARP][QPC];
    __shared__ float4 smean[QPC], sinv[QPC];

    const int cb   = blockIdx.x;                  // column block 0..3 (fastest)
    const int g    = blockIdx.y;                  // graph
    const int quad = threadIdx.x & (QPC - 1);     // 0..7
    const int rb   = threadIdx.x >> 3;            // 0..63
    const int warp = threadIdx.x >> 5;
    const int lane = threadIdx.x & 31;

    const int start = batch[g];
    const int end   = batch[g + 1];
    const int cnt   = end - start;
    const float fcnt = (float)cnt;

    const float4* __restrict__ xv = (const float4*)x;
    float4* __restrict__ ov = (float4*)out;
    const long colq = (long)cb * QPC + quad;      // float4 col 0..31

    // ---- pass 1: read slice (cached in L2), accumulate sum / sumsq ----
    float4 s = make_float4(0.f, 0.f, 0.f, 0.f);
    float4 q = make_float4(0.f, 0.f, 0.f, 0.f);
    for (int r = rb; r < cnt; r += RB) {
        float4 v = xv[(long)(start + r) * D4 + colq];
        s.x += v.x; s.y += v.y; s.z += v.z; s.w += v.w;
        q.x += v.x * v.x; q.y += v.y * v.y; q.z += v.z * v.z; q.w += v.w * v.w;
    }

    // ---- warp reduce: lanes {quad, quad+8, quad+16, quad+24} share a column ----
    #pragma unroll
    for (int off = 8; off <= 16; off <<= 1) {
        s.x += __shfl_xor_sync(0xffffffffu, s.x, off);
        s.y += __shfl_xor_sync(0xffffffffu, s.y, off);
        s.z += __shfl_xor_sync(0xffffffffu, s.z, off);
        s.w += __shfl_xor_sync(0xffffffffu, s.w, off);
        q.x += __shfl_xor_sync(0xffffffffu, q.x, off);
        q.y += __shfl_xor_sync(0xffffffffu, q.y, off);
        q.z += __shfl_xor_sync(0xffffffffu, q.z, off);
        q.w += __shfl_xor_sync(0xffffffffu, q.w, off);
    }
    if (lane < QPC) { psum[warp][quad] = s; psq[warp][quad] = q; }
    __syncthreads();

    // ---- final reduce across warps + stats (QPC threads) ----
    if (threadIdx.x < QPC) {
        float4 ts = make_float4(0.f, 0.f, 0.f, 0.f);
        float4 tq = make_float4(0.f, 0.f, 0.f, 0.f);
        #pragma unroll
        for (int w = 0; w < NWARP; w++) {
            float4 a = psum[w][threadIdx.x];
            float4 b = psq [w][threadIdx.x];
            ts.x += a.x; ts.y += a.y; ts.z += a.z; ts.w += a.w;
            tq.x += b.x; tq.y += b.y; tq.z += b.z; tq.w += b.w;
        }
        float4 m, iv;
        m.x = ts.x / fcnt; m.y = ts.y / fcnt; m.z = ts.z / fcnt; m.w = ts.w / fcnt;
        float denom = fcnt - 1.0f;
        iv.x = 1.0f / (sqrtf(fmaxf((tq.x - fcnt * m.x * m.x) / denom, 0.f)) + 1e-5f);
        iv.y = 1.0f / (sqrtf(fmaxf((tq.y - fcnt * m.y * m.y) / denom, 0.f)) + 1e-5f);
        iv.z = 1.0f / (sqrtf(fmaxf((tq.z - fcnt * m.z * m.z) / denom, 0.f)) + 1e-5f);
        iv.w = 1.0f / (sqrtf(fmaxf((tq.w - fcnt * m.w * m.w) / denom, 0.f)) + 1e-5f);
        smean[threadIdx.x] = m;
        sinv [threadIdx.x] = iv;
    }
    __syncthreads();

    // ---- pass 2: re-read slice (L2-resident; evict-first), streaming store ----
    const float4 g4 = ((const float4*)gamma)[colq];
    const float4 b4 = ((const float4*)beta)[colq];
    const float4 m  = smean[quad];
    const float4 iv = sinv [quad];

    for (int r = rb; r < cnt; r += RB) {
        const long idx = (long)(start + r) * D4 + colq;
        float4 v = __ldcs(&xv[idx]);          // L2 hit, mark evict-first (dead after)
        float4 o;
        o.x = g4.x * (v.x - m.x) * iv.x + b4.x;
        o.y = g4.y * (v.y - m.y) * iv.y + b4.y;
        o.z = g4.z * (v.z - m.z) * iv.z + b4.z;
        o.w = g4.w * (v.w - m.w) * iv.w + b4.w;
        __stcs(&ov[idx], o);                  // streaming store, don't pollute L2
    }
}

extern "C" void kernel_launch(void* const* d_in, const int* in_sizes, int n_in,
                              void* d_out, int out_size)
{
    const float* x     = (const float*)d_in[0];
    const float* gamma = (const float*)d_in[1];
    const float* beta  = (const float*)d_in[2];
    const int*   batch = (const int*)d_in[3];
    float* out = (float*)d_out;

    const int G = in_sizes[3] - 1;
    dim3 grid(D4 / QPC, G);   // (column-block fastest, graph)
    graphnorm_l2<<<grid, THREADS>>>(x, gamma, beta, batch, out);
}

// round 7
// speedup vs baseline: 1.2668x; 1.0316x over previous
#include <cuda_runtime.h>
#include <cuda_bf16.h>
#include <cstdint>

#define D4 32               // float4 per full row (D=128)
#define QPC 8               // float4-quads per CTA (32 cols = 128B contiguous/row)
#define NCB 4               // column blocks per row (D4/QPC)
#define THREADS 512
#define RB (THREADS / QPC)  // 64 row-bases
#define NWARP (THREADS / 32)
#define MAXSLOTS 16384      // (graph, column-block) slots

// scratch: per slot, 2 halves x (8 float4 sum + 8 float4 sq) = 32 float4
__device__ float4 g_part[MAXSLOTS * 32];
__device__ int    g_cnt [MAXSLOTS];

__global__ void zero_counters(int nslots) {
    int i = blockIdx.x * blockDim.x + threadIdx.x;
    if (i < nslots) g_cnt[i] = 0;
}

__global__ __launch_bounds__(THREADS, 4)
void graphnorm_split(const float* __restrict__ x,
                     const float* __restrict__ gamma,
                     const float* __restrict__ beta,
                     const int* __restrict__ batch,
                     float* __restrict__ out)
{
    __shared__ float4 psum[NWARP][QPC];
    __shared__ float4 psq [NWARP][QPC];
    __shared__ float4 smean[QPC], sinv[QPC];

    const int hf   = blockIdx.x & 1;              // row half 0/1 (fastest -> pair adjacent)
    const int cb   = blockIdx.x >> 1;             // column block 0..3
    const int g    = blockIdx.y;                  // graph
    const int slot = g * NCB + cb;
    const int quad = threadIdx.x & (QPC - 1);     // 0..7
    const int rb   = threadIdx.x >> 3;            // 0..63
    const int warp = threadIdx.x >> 5;
    const int lane = threadIdx.x & 31;

    const int start = batch[g];
    const int end   = batch[g + 1];
    const int cnt   = end - start;
    const float fcnt = (float)cnt;
    const int hlen    = cnt >> 1;
    const int myStart = start + hf * hlen;
    const int myCnt   = hf ? (cnt - hlen) : hlen;

    const float4* __restrict__ xv = (const float4*)x;
    float4* __restrict__ ov = (float4*)out;
    const long colq = (long)cb * QPC + quad;      // float4 col 0..31

    // ---- pass 1: read my 64KB slice (stays in L2), accumulate sum/sumsq ----
    float4 s = make_float4(0.f, 0.f, 0.f, 0.f);
    float4 q = make_float4(0.f, 0.f, 0.f, 0.f);
    for (int r = rb; r < myCnt; r += RB) {
        float4 v = xv[(long)(myStart + r) * D4 + colq];
        s.x += v.x; s.y += v.y; s.z += v.z; s.w += v.w;
        q.x += v.x * v.x; q.y += v.y * v.y; q.z += v.z * v.z; q.w += v.w * v.w;
    }

    // ---- warp reduce: lanes {quad, quad+8, quad+16, quad+24} share a column ----
    #pragma unroll
    for (int off = 8; off <= 16; off <<= 1) {
        s.x += __shfl_xor_sync(0xffffffffu, s.x, off);
        s.y += __shfl_xor_sync(0xffffffffu, s.y, off);
        s.z += __shfl_xor_sync(0xffffffffu, s.z, off);
        s.w += __shfl_xor_sync(0xffffffffu, s.w, off);
        q.x += __shfl_xor_sync(0xffffffffu, q.x, off);
        q.y += __shfl_xor_sync(0xffffffffu, q.y, off);
        q.z += __shfl_xor_sync(0xffffffffu, q.z, off);
        q.w += __shfl_xor_sync(0xffffffffu, q.w, off);
    }
    if (lane < QPC) { psum[warp][quad] = s; psq[warp][quad] = q; }
    __syncthreads();

    // ---- CTA reduce (threads 0..7) -> publish partial to gmem slot half ----
    if (threadIdx.x < QPC) {
        float4 ts = make_float4(0.f, 0.f, 0.f, 0.f);
        float4 tq = make_float4(0.f, 0.f, 0.f, 0.f);
        #pragma unroll
        for (int w = 0; w < NWARP; w++) {
            float4 a = psum[w][threadIdx.x];
            float4 b = psq [w][threadIdx.x];
            ts.x += a.x; ts.y += a.y; ts.z += a.z; ts.w += a.w;
            tq.x += b.x; tq.y += b.y; tq.z += b.z; tq.w += b.w;
        }
        float4* base = &g_part[(long)slot * 32 + hf * 16];
        base[threadIdx.x]     = ts;
        base[threadIdx.x + 8] = tq;
    }
    __syncthreads();   // all partial stores issued before the release-arrive

    // ---- arrive + spin until both halves published ----
    if (threadIdx.x == 0) {
        asm volatile("red.add.release.gpu.global.s32 [%0], 1;"
                     :: "l"(&g_cnt[slot]) : "memory");
        int v;
        do {
            asm volatile("ld.acquire.gpu.global.s32 %0, [%1];"
                         : "=r"(v) : "l"(&g_cnt[slot]) : "memory");
        } while (v < 2);
    }
    __syncthreads();

    // ---- combine both halves (fixed order: deterministic), compute stats ----
    if (threadIdx.x < QPC) {
        const float4* p0 = &g_part[(long)slot * 32];
        const float4* p1 = &g_part[(long)slot * 32 + 16];
        float4 a0 = p0[threadIdx.x],     a1 = p1[threadIdx.x];
        float4 b0 = p0[threadIdx.x + 8], b1 = p1[threadIdx.x + 8];
        float4 ts, tq;
        ts.x = a0.x + a1.x; ts.y = a0.y + a1.y; ts.z = a0.z + a1.z; ts.w = a0.w + a1.w;
        tq.x = b0.x + b1.x; tq.y = b0.y + b1.y; tq.z = b0.z + b1.z; tq.w = b0.w + b1.w;

        float4 m, iv;
        m.x = ts.x / fcnt; m.y = ts.y / fcnt; m.z = ts.z / fcnt; m.w = ts.w / fcnt;
        float denom = fcnt - 1.0f;
        iv.x = 1.0f / (sqrtf(fmaxf((tq.x - fcnt * m.x * m.x) / denom, 0.f)) + 1e-5f);
        iv.y = 1.0f / (sqrtf(fmaxf((tq.y - fcnt * m.y * m.y) / denom, 0.f)) + 1e-5f);
        iv.z = 1.0f / (sqrtf(fmaxf((tq.z - fcnt * m.z * m.z) / denom, 0.f)) + 1e-5f);
        iv.w = 1.0f / (sqrtf(fmaxf((tq.w - fcnt * m.w * m.w) / denom, 0.f)) + 1e-5f);
        smean[threadIdx.x] = m;
        sinv [threadIdx.x] = iv;
    }
    __syncthreads();

    // ---- pass 2: re-read slice (L2-resident, evict-first), streaming store ----
    const float4 g4 = ((const float4*)gamma)[colq];
    const float4 b4 = ((const float4*)beta)[colq];
    const float4 m  = smean[quad];
    const float4 iv = sinv [quad];

    for (int r = rb; r < myCnt; r += RB) {
        const long idx = (long)(myStart + r) * D4 + colq;
        float4 v = __ldcs(&xv[idx]);
        float4 o;
        o.x = g4.x * (v.x - m.x) * iv.x + b4.x;
        o.y = g4.y * (v.y - m.y) * iv.y + b4.y;
        o.z = g4.z * (v.z - m.z) * iv.z + b4.z;
        o.w = g4.w * (v.w - m.w) * iv.w + b4.w;
        __stcs(&ov[idx], o);
    }
}

extern "C" void kernel_launch(void* const* d_in, const int* in_sizes, int n_in,
                              void* d_out, int out_size)
{
    const float* x     = (const float*)d_in[0];
    const float* gamma = (const float*)d_in[1];
    const float* beta  = (const float*)d_in[2];
    const int*   batch = (const int*)d_in[3];
    float* out = (float*)d_out;

    const int G = in_sizes[3] - 1;
    const int nslots = G * NCB;

    zero_counters<<<(nslots + 255) / 256, 256>>>(nslots);

    dim3 grid(2 * NCB, G);   // x = (cb, half) with half fastest -> pairs adjacent
    graphnorm_split<<<grid, THREADS>>>(x, gamma, beta, batch, out);
}